// round 1
// baseline (speedup 1.0000x reference)
#include <cuda_runtime.h>

#define NNODES 65536
#define NEDGES 131072
#define BATCH  2048
#define NIN    64
#define EIN    16
#define H      300
#define DEPTH  3

// Scratch (static device globals; allocation inside kernel_launch is forbidden)
__device__ float g_h  [(size_t)NNODES * H];   //  78.6 MB
__device__ float g_eh [(size_t)NEDGES * H];   // 157.3 MB
__device__ float g_agg[(size_t)NNODES * H];   //  78.6 MB
__device__ float g_t  [(size_t)NNODES * H];   //  78.6 MB
__device__ float g_pool[3 * BATCH * H];       //   7.4 MB

// ---------------------------------------------------------------------------

__global__ void k_zero_pool() {
    int i = blockIdx.x * blockDim.x + threadIdx.x;
    if (i < 3 * BATCH * H) g_pool[i] = 0.f;
}

// h = relu(x @ Wn + bn)   [N,64] @ [64,300]
__global__ void k_node_proj(const float* __restrict__ x,
                            const float* __restrict__ Wn,
                            const float* __restrict__ bn) {
    __shared__ float xs[NIN];
    int n = blockIdx.x, t = threadIdx.x;
    if (t < NIN) xs[t] = x[n * NIN + t];
    __syncthreads();
    for (int j = t; j < H; j += blockDim.x) {
        float acc = bn[j];
#pragma unroll 16
        for (int k = 0; k < NIN; k++) acc = fmaf(xs[k], Wn[k * H + j], acc);
        g_h[(size_t)n * H + j] = fmaxf(acc, 0.f);
    }
}

// eh = e @ We + be   [E,16] @ [16,300]
__global__ void k_edge_proj(const float* __restrict__ e,
                            const float* __restrict__ We,
                            const float* __restrict__ be) {
    __shared__ float es[EIN];
    int ed = blockIdx.x, t = threadIdx.x;
    if (t < EIN) es[t] = e[ed * EIN + t];
    __syncthreads();
    if (t < H) {
        float acc = be[t];
#pragma unroll
        for (int k = 0; k < EIN; k++) acc = fmaf(es[k], We[k * H + t], acc);
        g_eh[(size_t)ed * H + t] = acc;
    }
}

// agg = h  (so after scatter, agg holds z = h + sum relu(h[src]+eh))
__global__ void k_copy_h_to_agg() {
    size_t i = (size_t)blockIdx.x * blockDim.x + threadIdx.x;
    if (i < (size_t)NNODES * H) g_agg[i] = g_h[i];
}

// agg[dst] += relu(h[src] + eh)   one block per edge
__global__ void k_scatter(const int* __restrict__ src, const int* __restrict__ dst) {
    int ed = blockIdx.x, t = threadIdx.x;
    if (t >= H) return;
    int s = src[ed], d = dst[ed];
    float v = g_h[(size_t)s * H + t] + g_eh[(size_t)ed * H + t];
    v = fmaxf(v, 0.f);
    atomicAdd(&g_agg[(size_t)d * H + t], v);
}

// C[N,300] = act(A[N,300] @ W[300,300] + bias)
// inSel: 0 -> g_agg, 1 -> g_t ; outSel: 0 -> g_t, 1 -> g_h
// BM=128, BN=64, BK=16, 256 threads, thread tile 8x4
template<bool RELU>
__global__ void k_gemm(int inSel, const float* __restrict__ W,
                       const float* __restrict__ bias, int outSel) {
    const int BM = 128, BN = 64, BK = 16;
    __shared__ float As[BK * (BM + 1)];   // [k][r], pad to kill store conflicts
    __shared__ float Ws[BK][BN];          // [k][c]

    const float* __restrict__ A = inSel ? g_t : g_agg;
    float* __restrict__ C = outSel ? g_h : g_t;

    int t = threadIdx.x;
    int ty = t >> 4, tx = t & 15;
    int row0 = blockIdx.x * BM, col0 = blockIdx.y * BN;

    float acc[8][4];
#pragma unroll
    for (int i = 0; i < 8; i++)
#pragma unroll
        for (int j = 0; j < 4; j++) acc[i][j] = 0.f;

    for (int kk = 0; kk < H; kk += BK) {
#pragma unroll
        for (int i = 0; i < 8; i++) {           // A tile: 128x16
            int idx = t + i * 256;
            int r = idx >> 4, k = idx & 15;
            int gk = kk + k;
            As[k * (BM + 1) + r] = (gk < H) ? A[(size_t)(row0 + r) * H + gk] : 0.f;
        }
#pragma unroll
        for (int i = 0; i < 4; i++) {           // W tile: 16x64
            int idx = t + i * 256;
            int k = idx >> 6, c = idx & 63;
            int gk = kk + k, gc = col0 + c;
            Ws[k][c] = (gk < H && gc < H) ? W[(size_t)gk * H + gc] : 0.f;
        }
        __syncthreads();
#pragma unroll
        for (int k = 0; k < BK; k++) {
            float4 w = *reinterpret_cast<float4*>(&Ws[k][tx * 4]);
#pragma unroll
            for (int i = 0; i < 8; i++) {
                float a = As[k * (BM + 1) + ty * 8 + i];
                acc[i][0] = fmaf(a, w.x, acc[i][0]);
                acc[i][1] = fmaf(a, w.y, acc[i][1]);
                acc[i][2] = fmaf(a, w.z, acc[i][2]);
                acc[i][3] = fmaf(a, w.w, acc[i][3]);
            }
        }
        __syncthreads();
    }

#pragma unroll
    for (int j = 0; j < 4; j++) {
        int c = col0 + tx * 4 + j;
        if (c >= H) continue;
        float b = bias[c];
#pragma unroll
        for (int i = 0; i < 8; i++) {
            float v = acc[i][j] + b;
            if (RELU) v = fmaxf(v, 0.f);
            C[(size_t)(row0 + ty * 8 + i) * H + c] = v;
        }
    }
}

// pool[which][seg[n]] += h[n]
__global__ void k_pool(const int* __restrict__ seg, int which) {
    int n = blockIdx.x, t = threadIdx.x;
    if (t >= H) return;
    int b = seg[n];
    atomicAdd(&g_pool[(size_t)(which * BATCH + b) * H + t], g_h[(size_t)n * H + t]);
}

// out = [reactants - products | reactants | products]
__global__ void k_combine(float* __restrict__ out) {
    int i = blockIdx.x * blockDim.x + threadIdx.x;
    if (i >= BATCH * H) return;
    float r = g_pool[i] + g_pool[BATCH * H + i];
    float p = g_pool[2 * BATCH * H + i];
    out[i] = r - p;
    out[BATCH * H + i] = r;
    out[2 * BATCH * H + i] = p;
}

// ---------------------------------------------------------------------------

extern "C" void kernel_launch(void* const* d_in, const int* in_sizes, int n_in,
                              void* d_out, int out_size) {
    // metadata order: (x,e,src,dst,seg) x {r1,r2,p1}, then Wn,bn,We,be,W1,b1,W2,b2
    const float* Wn = (const float*)d_in[15];
    const float* bn = (const float*)d_in[16];
    const float* We = (const float*)d_in[17];
    const float* be = (const float*)d_in[18];
    const float* W1 = (const float*)d_in[19];
    const float* b1 = (const float*)d_in[20];
    const float* W2 = (const float*)d_in[21];
    const float* b2 = (const float*)d_in[22];

    k_zero_pool<<<(3 * BATCH * H + 255) / 256, 256>>>();

    dim3 ggrid(NNODES / 128, (H + 63) / 64);

    for (int g = 0; g < 3; g++) {
        const float* x   = (const float*)d_in[g * 5 + 0];
        const float* e   = (const float*)d_in[g * 5 + 1];
        const int*   src = (const int*)  d_in[g * 5 + 2];
        const int*   dst = (const int*)  d_in[g * 5 + 3];
        const int*   seg = (const int*)  d_in[g * 5 + 4];

        k_node_proj<<<NNODES, 256>>>(x, Wn, bn);
        k_edge_proj<<<NEDGES, 320>>>(e, We, be);

        for (int l = 0; l < DEPTH; l++) {
            k_copy_h_to_agg<<<(int)(((size_t)NNODES * H + 255) / 256), 256>>>();
            k_scatter<<<NEDGES, 320>>>(src, dst);
            // t = relu(z @ W1[l] + b1[l])
            k_gemm<true><<<ggrid, 256>>>(0, W1 + (size_t)l * H * H, b1 + (size_t)l * H, 0);
            // h = t @ W2[l] + b2[l]  (relu between layers only)
            if (l < DEPTH - 1)
                k_gemm<true><<<ggrid, 256>>>(1, W2 + (size_t)l * H * H, b2 + (size_t)l * H, 1);
            else
                k_gemm<false><<<ggrid, 256>>>(1, W2 + (size_t)l * H * H, b2 + (size_t)l * H, 1);
        }
        k_pool<<<NNODES, 320>>>(seg, g);
    }
    k_combine<<<(BATCH * H + 255) / 256, 256>>>((float*)d_out);
}

// round 3
// speedup vs baseline: 2.5948x; 2.5948x over previous
#include <cuda_runtime.h>
#include <cstdint>

#define NNODES 65536
#define NEDGES 131072
#define BATCH  2048
#define H      300
#define H4     75
#define DEPTH  3

// Scratch (static device globals; allocation inside kernel_launch is forbidden)
__device__ __align__(16) float g_h  [(size_t)NNODES * H];
__device__ __align__(16) float g_eh [(size_t)NEDGES * H];
__device__ __align__(16) float g_agg[(size_t)NNODES * H];
__device__ __align__(16) float g_t  [(size_t)NNODES * H];
__device__ __align__(16) float g_pool[3 * BATCH * H];

// ---------------------------------------------------------------------------
// helpers

__device__ __forceinline__ uint32_t f2tf32(float f) {
    uint32_t u;
    asm("cvt.rna.tf32.f32 %0, %1;" : "=r"(u) : "f"(f));
    return u;
}

__device__ __forceinline__ void mma_tf32(float& d0, float& d1, float& d2, float& d3,
                                         uint32_t a0, uint32_t a1, uint32_t a2, uint32_t a3,
                                         uint32_t b0, uint32_t b1) {
    asm volatile(
        "mma.sync.aligned.m16n8k8.row.col.f32.tf32.tf32.f32 "
        "{%0,%1,%2,%3},{%4,%5,%6,%7},{%8,%9},{%0,%1,%2,%3};"
        : "+f"(d0), "+f"(d1), "+f"(d2), "+f"(d3)
        : "r"(a0), "r"(a1), "r"(a2), "r"(a3), "r"(b0), "r"(b1));
}

__device__ __forceinline__ void red4(float4* p, float4 v) {
    asm volatile("red.global.add.v4.f32 [%0], {%1,%2,%3,%4};"
                 :: "l"(p), "f"(v.x), "f"(v.y), "f"(v.z), "f"(v.w) : "memory");
}

// ---------------------------------------------------------------------------
// TF32 tensor-core GEMM: C[M,300] = act(A[M,K] @ W[K,300] + bias)
// BM=128, BN=64, BK=32, 256 threads (8 warps as 4x2), warp tile 32x32 via
// 2x4 mma.m16n8k8.  aSel: 0 -> Aext, 1 -> g_agg, 2 -> g_t
//                   oSel: 0 -> g_t,  1 -> g_h (+g_agg if DUAL), 2 -> g_eh
template<bool RELU, bool DUAL>
__global__ __launch_bounds__(256) void k_gemm_tf32(
    const float* __restrict__ Aext, int aSel, int lda, int K,
    const float* __restrict__ W, const float* __restrict__ bias, int oSel)
{
    __shared__ uint32_t As[128 * 36];  // [m][k], stride 36 -> conflict-free frags
    __shared__ uint32_t Ws[64 * 36];   // [n][k], stride 36 -> conflict-free frags

    const float* __restrict__ A = (aSel == 0) ? Aext : (aSel == 1) ? g_agg : g_t;
    float* __restrict__ out1 = (oSel == 0) ? g_t : (oSel == 1) ? g_h : g_eh;
    float* __restrict__ out2 = g_agg;

    int t = threadIdx.x;
    int lane = t & 31, warp = t >> 5;
    int warpM = warp >> 1, warpN = warp & 1;
    int row0 = blockIdx.y * 128, col0 = blockIdx.x * 64;

    float d[2][4][4];
#pragma unroll
    for (int i = 0; i < 2; i++)
#pragma unroll
        for (int j = 0; j < 4; j++)
#pragma unroll
            for (int q = 0; q < 4; q++) d[i][j][q] = 0.f;

    for (int kk = 0; kk < K; kk += 32) {
        // stage A tile 128x32 (float4, convert to tf32)
#pragma unroll
        for (int i = 0; i < 4; i++) {
            int idx = t + i * 256;
            int r = idx >> 3, f4 = idx & 7;
            int gk = kk + f4 * 4;
            float4 v = make_float4(0.f, 0.f, 0.f, 0.f);
            if (gk < K) v = *(const float4*)(A + (size_t)(row0 + r) * lda + gk);
            uint4 u;
            u.x = f2tf32(v.x); u.y = f2tf32(v.y); u.z = f2tf32(v.z); u.w = f2tf32(v.w);
            *(uint4*)&As[r * 36 + f4 * 4] = u;
        }
        // stage W tile 32x64 transposed into [n][k]
#pragma unroll
        for (int i = 0; i < 8; i++) {
            int idx = t + i * 256;
            int k = idx >> 6, c = idx & 63;
            int gk = kk + k, gc = col0 + c;
            float v = (gk < K && gc < H) ? W[(size_t)gk * H + gc] : 0.f;
            Ws[c * 36 + k] = f2tf32(v);
        }
        __syncthreads();

#pragma unroll
        for (int ks = 0; ks < 4; ks++) {
            int kb = ks * 8 + (lane & 3);
            uint32_t a[2][4], b[4][2];
#pragma unroll
            for (int mt = 0; mt < 2; mt++) {
                int mr = warpM * 32 + mt * 16 + (lane >> 2);
                a[mt][0] = As[mr * 36 + kb];
                a[mt][1] = As[(mr + 8) * 36 + kb];
                a[mt][2] = As[mr * 36 + kb + 4];
                a[mt][3] = As[(mr + 8) * 36 + kb + 4];
            }
#pragma unroll
            for (int nt = 0; nt < 4; nt++) {
                int nc = warpN * 32 + nt * 8 + (lane >> 2);
                b[nt][0] = Ws[nc * 36 + kb];
                b[nt][1] = Ws[nc * 36 + kb + 4];
            }
#pragma unroll
            for (int mt = 0; mt < 2; mt++)
#pragma unroll
                for (int nt = 0; nt < 4; nt++)
                    mma_tf32(d[mt][nt][0], d[mt][nt][1], d[mt][nt][2], d[mt][nt][3],
                             a[mt][0], a[mt][1], a[mt][2], a[mt][3],
                             b[nt][0], b[nt][1]);
        }
        __syncthreads();
    }

    // epilogue: bias (+relu), float2 stores, optional dual store
#pragma unroll
    for (int nt = 0; nt < 4; nt++) {
        int col = col0 + warpN * 32 + nt * 8 + (lane & 3) * 2;
        if (col >= H) continue;
        float2 bs = *(const float2*)(bias + col);
#pragma unroll
        for (int mt = 0; mt < 2; mt++) {
            int r = row0 + warpM * 32 + mt * 16 + (lane >> 2);
            float v0 = d[mt][nt][0] + bs.x;
            float v1 = d[mt][nt][1] + bs.y;
            float v2 = d[mt][nt][2] + bs.x;
            float v3 = d[mt][nt][3] + bs.y;
            if (RELU) {
                v0 = fmaxf(v0, 0.f); v1 = fmaxf(v1, 0.f);
                v2 = fmaxf(v2, 0.f); v3 = fmaxf(v3, 0.f);
            }
            float2 p0 = make_float2(v0, v1);
            float2 p1 = make_float2(v2, v3);
            *(float2*)(out1 + (size_t)r * H + col) = p0;
            *(float2*)(out1 + (size_t)(r + 8) * H + col) = p1;
            if (DUAL) {
                *(float2*)(out2 + (size_t)r * H + col) = p0;
                *(float2*)(out2 + (size_t)(r + 8) * H + col) = p1;
            }
        }
    }
}

// ---------------------------------------------------------------------------
// agg[dst] += relu(h[src] + eh)   one warp per edge, float4 vector atomics
__global__ __launch_bounds__(256) void k_scatter(const int* __restrict__ src,
                                                 const int* __restrict__ dst) {
    int e = blockIdx.x * 8 + (threadIdx.x >> 5);
    int lane = threadIdx.x & 31;
    int s = __ldg(src + e), dn = __ldg(dst + e);
    const float4* hp = (const float4*)g_h + (size_t)s * H4;
    const float4* ep = (const float4*)g_eh + (size_t)e * H4;
    float4* ap = (float4*)g_agg + (size_t)dn * H4;
#pragma unroll 3
    for (int c = lane; c < H4; c += 32) {
        float4 h = hp[c], ev = ep[c];
        float4 v;
        v.x = fmaxf(h.x + ev.x, 0.f);
        v.y = fmaxf(h.y + ev.y, 0.f);
        v.z = fmaxf(h.z + ev.z, 0.f);
        v.w = fmaxf(h.w + ev.w, 0.f);
        red4(ap + c, v);
    }
}

// ---------------------------------------------------------------------------
// pool[which][b] = sum of h rows [32b, 32b+32)  (seg is repeat(arange(B),32))
__global__ __launch_bounds__(128) void k_pool(int which) {
    int b = blockIdx.x;
    int c = threadIdx.x;
    if (c >= H4) return;
    const float4* hp = (const float4*)g_h + (size_t)b * 32 * H4;
    float4 acc = make_float4(0.f, 0.f, 0.f, 0.f);
#pragma unroll
    for (int n = 0; n < 32; n++) {
        float4 v = hp[(size_t)n * H4 + c];
        acc.x += v.x; acc.y += v.y; acc.z += v.z; acc.w += v.w;
    }
    ((float4*)g_pool)[(size_t)(which * BATCH + b) * H4 + c] = acc;
}

// out = [reactants - products | reactants | products]
__global__ void k_combine(float* __restrict__ out) {
    int i = blockIdx.x * blockDim.x + threadIdx.x;
    if (i >= BATCH * H) return;
    float r = g_pool[i] + g_pool[BATCH * H + i];
    float p = g_pool[2 * BATCH * H + i];
    out[i] = r - p;
    out[BATCH * H + i] = r;
    out[2 * BATCH * H + i] = p;
}

// ---------------------------------------------------------------------------

extern "C" void kernel_launch(void* const* d_in, const int* in_sizes, int n_in,
                              void* d_out, int out_size) {
    // (x,e,src,dst,seg) x {r1,r2,p1}, then Wn,bn,We,be,W1,b1,W2,b2
    const float* Wn = (const float*)d_in[15];
    const float* bn = (const float*)d_in[16];
    const float* We = (const float*)d_in[17];
    const float* be = (const float*)d_in[18];
    const float* W1 = (const float*)d_in[19];
    const float* b1 = (const float*)d_in[20];
    const float* W2 = (const float*)d_in[21];
    const float* b2 = (const float*)d_in[22];

    dim3 gN(5, NNODES / 128);   // node-rows GEMM grid (N-major for L2 A-reuse)
    dim3 gE(5, NEDGES / 128);   // edge-rows GEMM grid

    for (int g = 0; g < 3; g++) {
        const float* x   = (const float*)d_in[g * 5 + 0];
        const float* e   = (const float*)d_in[g * 5 + 1];
        const int*   src = (const int*)  d_in[g * 5 + 2];
        const int*   dst = (const int*)  d_in[g * 5 + 3];

        // h = relu(x @ Wn + bn), dual-stored into g_h AND g_agg (layer-0 base)
        k_gemm_tf32<true, true><<<gN, 256>>>(x, 0, 64, 64, Wn, bn, 1);
        // eh = e @ We + be
        k_gemm_tf32<false, false><<<gE, 256>>>(e, 0, 16, 16, We, be, 2);

        for (int l = 0; l < DEPTH; l++) {
            // agg (= h, from dual store) += relu(h[src] + eh)
            k_scatter<<<NEDGES / 8, 256>>>(src, dst);
            // t = relu(z @ W1[l] + b1[l])  with z = agg
            k_gemm_tf32<true, false><<<gN, 256>>>(
                nullptr, 1, H, H, W1 + (size_t)l * H * H, b1 + (size_t)l * H, 0);
            // h = (relu?)(t @ W2[l] + b2[l]); mid layers dual-store into agg too
            if (l < DEPTH - 1)
                k_gemm_tf32<true, true><<<gN, 256>>>(
                    nullptr, 2, H, H, W2 + (size_t)l * H * H, b2 + (size_t)l * H, 1);
            else
                k_gemm_tf32<false, false><<<gN, 256>>>(
                    nullptr, 2, H, H, W2 + (size_t)l * H * H, b2 + (size_t)l * H, 1);
        }
        k_pool<<<BATCH, 128>>>(g);
    }
    k_combine<<<(BATCH * H + 255) / 256, 256>>>((float*)d_out);
}